// round 5
// baseline (speedup 1.0000x reference)
#include <cuda_runtime.h>

#define N 4096
#define NN (N * N)
#define NITERS 300
#define NBLK 128
#define TPB 1024
#define THR 44.0f          // skip chunks more than THR log2-units below row max bound

__device__ float  d_B[NN];          // raw distances (sorted order), 64MB
__device__ float  d_xs[3 * N];      // Morton-sorted pc1
__device__ float  d_ys[3 * N];      // Morton-sorted pc2
__device__ float  d_minBF[N * 32];  // per row: min dist over each 128-col chunk
__device__ float  d_minBC[128 * 32];// per 32-col tile: min dist over each 128-row chunk
__device__ float  d_F[N];
__device__ float  d_G[N];
__device__ double d_csum;
__device__ double d_emd;
__device__ float  d_k;              // log2(e)/eps
__device__ unsigned int g_bar;
__device__ unsigned int g_epoch;

__device__ __forceinline__ float ex2f(float x) {
    float y;
    asm("ex2.approx.ftz.f32 %0, %1;" : "=f"(y) : "f"(x));
    return y;
}
__device__ __forceinline__ float ldcg(const float* p) { return __ldcg(p); }

// ---------------------------------------------------------------- init
__global__ void k_init() {
    d_csum  = 0.0;
    d_emd   = 0.0;
    g_bar   = 0u;
    g_epoch = 0u;
}

// ---------------------------------------------------------------- Morton sort (one block)
__device__ __forceinline__ unsigned expand10(unsigned v) {
    v &= 0x3FFu;
    v = (v | (v << 16)) & 0x030000FFu;
    v = (v | (v << 8))  & 0x0300F00Fu;
    v = (v | (v << 4))  & 0x030C30C3u;
    v = (v | (v << 2))  & 0x09249249u;
    return v;
}
__global__ void __launch_bounds__(1024, 1) k_sort(const float* __restrict__ in,
                                                  float* __restrict__ outp) {
    __shared__ unsigned sk[N];
    __shared__ unsigned short si[N];
    int tid = threadIdx.x;
    for (int r = tid; r < N; r += 1024) {
        float a = in[3 * r], b = in[3 * r + 1], c = in[3 * r + 2];
        unsigned ua = (unsigned)fminf(fmaxf((a + 5.0f) * 102.3f, 0.0f), 1023.0f);
        unsigned ub = (unsigned)fminf(fmaxf((b + 5.0f) * 102.3f, 0.0f), 1023.0f);
        unsigned uc = (unsigned)fminf(fmaxf((c + 5.0f) * 102.3f, 0.0f), 1023.0f);
        sk[r] = expand10(ua) | (expand10(ub) << 1) | (expand10(uc) << 2);
        si[r] = (unsigned short)r;
    }
    __syncthreads();
    for (int ksz = 2; ksz <= N; ksz <<= 1) {
        for (int stride = ksz >> 1; stride > 0; stride >>= 1) {
            for (int p = tid; p < N / 2; p += 1024) {
                int lo = ((p & ~(stride - 1)) << 1) | (p & (stride - 1));
                int hi = lo | stride;
                bool up = ((lo & ksz) == 0);
                unsigned ka = sk[lo], kb = sk[hi];
                if ((ka > kb) == up) {
                    sk[lo] = kb; sk[hi] = ka;
                    unsigned short t = si[lo]; si[lo] = si[hi]; si[hi] = t;
                }
            }
            __syncthreads();
        }
    }
    for (int r = tid; r < N; r += 1024) {
        int s = si[r];
        outp[3 * r]     = in[3 * s];
        outp[3 * r + 1] = in[3 * s + 1];
        outp[3 * r + 2] = in[3 * s + 2];
    }
}

// ---------------------------------------------------------------- distance helper
__device__ __forceinline__ float distf(float x0, float x1, float x2, float xx,
                                       float y0, float y1, float y2) {
    float yy  = y0 * y0 + y1 * y1 + y2 * y2;
    float dot = x0 * y0 + x1 * y1 + x2 * y2;
    float d2  = xx + yy - 2.0f * dot;
    return sqrtf(fmaxf(d2, 0.0f) + 1e-12f);
}

// ---------------------------------------------------------------- csum; zero F/G
__global__ void k_sum(const float* __restrict__ x, const float* __restrict__ y) {
    __shared__ float sred[8];
    int i = blockIdx.x;
    float x0 = x[3 * i], x1 = x[3 * i + 1], x2 = x[3 * i + 2];
    float xx = x0 * x0 + x1 * x1 + x2 * x2;
    float acc = 0.0f;
    for (int j = threadIdx.x; j < N; j += 256)
        acc += distf(x0, x1, x2, xx, y[3 * j], y[3 * j + 1], y[3 * j + 2]);
    for (int o = 16; o; o >>= 1) acc += __shfl_down_sync(0xffffffffu, acc, o);
    if ((threadIdx.x & 31) == 0) sred[threadIdx.x >> 5] = acc;
    __syncthreads();
    if (threadIdx.x < 8) {
        acc = sred[threadIdx.x];
        for (int o = 4; o; o >>= 1) acc += __shfl_down_sync(0xffu, acc, o);
        if (threadIdx.x == 0) atomicAdd(&d_csum, (double)acc);
    }
    if (threadIdx.x == 0) { d_F[i] = 0.0f; d_G[i] = 0.0f; }
}

// ---------------------------------------------------------------- eps -> k
__global__ void k_eps() {
    double mean = d_csum / (double)NN;
    d_k = (float)(1.4426950408889634 / (0.02 * mean));
}

// ---------------------------------------------------------------- build B + row-chunk mins
__global__ void k_build(const float* __restrict__ x, const float* __restrict__ y) {
    __shared__ int sMin[32];
    int i = blockIdx.x, tid = threadIdx.x;
    if (tid < 32) sMin[tid] = 0x7F7FFFFF;
    __syncthreads();
    float x0 = x[3 * i], x1 = x[3 * i + 1], x2 = x[3 * i + 2];
    float xx = x0 * x0 + x1 * x1 + x2 * x2;
    for (int m = 0; m < 16; m++) {
        int j = tid + 256 * m;
        float c = distf(x0, x1, x2, xx, y[3 * j], y[3 * j + 1], y[3 * j + 2]);
        d_B[(size_t)i * N + j] = c;
        float w = c;
        for (int o = 16; o; o >>= 1) w = fminf(w, __shfl_xor_sync(0xffffffffu, w, o));
        if ((tid & 31) == 0) atomicMin(&sMin[j >> 7], __float_as_int(w));
    }
    __syncthreads();
    if (tid < 32) d_minBF[i * 32 + tid] = __int_as_float(sMin[tid]);
}

// ---------------------------------------------------------------- column-tile row-chunk mins
__global__ void __launch_bounds__(1024, 1) k_minc() {
    __shared__ float sM[32][33];
    int tx = threadIdx.x & 31, ty = threadIdx.x >> 5;
    int j = blockIdx.x * 32 + tx;
    for (int rc = 0; rc < 32; rc++) {
        int i0 = rc * 128 + ty;
        float v = fminf(fminf(d_B[(size_t)i0 * N + j],        d_B[(size_t)(i0 + 32) * N + j]),
                        fminf(d_B[(size_t)(i0 + 64) * N + j], d_B[(size_t)(i0 + 96) * N + j]));
        sM[ty][tx] = v;
        __syncthreads();
        for (int o = 16; o; o >>= 1) {
            if (ty < o) sM[ty][tx] = fminf(sM[ty][tx], sM[ty + o][tx]);
            __syncthreads();
        }
        if (ty == 0) {
            float m = sM[0][tx];
            for (int o = 16; o; o >>= 1) m = fminf(m, __shfl_xor_sync(0xffffffffu, m, o));
            if (tx == 0) d_minBC[blockIdx.x * 32 + rc] = m;
        }
        __syncthreads();
    }
}

// ---------------------------------------------------------------- grid barrier
__device__ __forceinline__ void gsync(unsigned int& ep) {
    __syncthreads();
    if (threadIdx.x == 0) {
        unsigned int t;
        asm volatile("atom.add.release.gpu.u32 %0, [%1], 1;"
                     : "=r"(t) : "l"(&g_bar) : "memory");
        if (t == NBLK - 1) {
            g_bar = 0u;
            asm volatile("st.release.gpu.u32 [%0], %1;"
                         :: "l"(&g_epoch), "r"(ep + 1u) : "memory");
        } else {
            unsigned int v;
            do {
                asm volatile("ld.acquire.gpu.u32 %0, [%1];"
                             : "=r"(v) : "l"(&g_epoch) : "memory");
            } while (v == ep);
        }
    }
    ep++;
    __syncthreads();
}

// ---------------------------------------------------------------- persistent Sinkhorn + final
__global__ void __launch_bounds__(TPB, 1) k_persist(float* __restrict__ out) {
    __shared__ float sV[N];
    __shared__ float sr[32][33];
    __shared__ float sMax[32];
    const int tid = threadIdx.x;
    const int bid = blockIdx.x;
    const int wid = tid >> 5;
    const int ln  = tid & 31;
    const float k = d_k;
    unsigned int ep = 0u;

    for (int it = 0; it < NITERS; it++) {
        // ---- f pass: warp-per-row with chunk skipping
        for (int j = tid; j < N; j += TPB) sV[j] = ldcg(&d_G[j]);
        __syncthreads();
        {   // chunk-max of G: warp wid -> chunk wid (128 vals)
            float m = fmaxf(fmaxf(sV[wid * 128 + ln],      sV[wid * 128 + ln + 32]),
                            fmaxf(sV[wid * 128 + ln + 64], sV[wid * 128 + ln + 96]));
            for (int o = 16; o; o >>= 1) m = fmaxf(m, __shfl_xor_sync(0xffffffffu, m, o));
            if (ln == 0) sMax[wid] = m;
        }
        __syncthreads();
        {
            const int i = bid * 32 + wid;
            const float Fi = ldcg(&d_F[i]);
            const float c  = Fi - 12.0f;
            float bnd = sMax[ln] - k * d_minBF[i * 32 + ln];       // per-lane chunk bound
            float rm  = bnd;
            for (int o = 16; o; o >>= 1) rm = fmaxf(rm, __shfl_xor_sync(0xffffffffu, rm, o));
            unsigned mask = __ballot_sync(0xffffffffu, bnd >= rm - THR);

            const float4* Br = (const float4*)(d_B + (size_t)i * N);
            const float4* V4 = (const float4*)sV;
            float s0 = 0.f, s1 = 0.f, s2 = 0.f, s3 = 0.f;
            for (int s = 0; s < 32; s++) {
                if (!((mask >> s) & 1u)) continue;
                int t = s * 32 + ln;
                float4 b = Br[t];
                float4 g = V4[t];
                s0 += ex2f(fmaf(-k, b.x, g.x + c));
                s1 += ex2f(fmaf(-k, b.y, g.y + c));
                s2 += ex2f(fmaf(-k, b.z, g.z + c));
                s3 += ex2f(fmaf(-k, b.w, g.w + c));
            }
            float s = (s0 + s1) + (s2 + s3);
            for (int o = 16; o; o >>= 1) s += __shfl_down_sync(0xffffffffu, s, o);
            if (ln == 0) d_F[i] = Fi - log2f(s);
        }
        gsync(ep);

        // ---- g pass: block-per-32-cols with row-chunk skipping
        for (int i = tid; i < N; i += TPB) sV[i] = ldcg(&d_F[i]);
        __syncthreads();
        {
            float m = fmaxf(fmaxf(sV[wid * 128 + ln],      sV[wid * 128 + ln + 32]),
                            fmaxf(sV[wid * 128 + ln + 64], sV[wid * 128 + ln + 96]));
            for (int o = 16; o; o >>= 1) m = fmaxf(m, __shfl_xor_sync(0xffffffffu, m, o));
            if (ln == 0) sMax[wid] = m;
        }
        __syncthreads();
        {
            const int tx = ln, ty = wid;
            const int j  = bid * 32 + tx;
            const float Gj = ldcg(&d_G[j]);
            const float c  = Gj - 12.0f;
            float bnd = sMax[ln] - k * d_minBC[bid * 32 + ln];
            float rm  = bnd;
            for (int o = 16; o; o >>= 1) rm = fmaxf(rm, __shfl_xor_sync(0xffffffffu, rm, o));
            unsigned mask = __ballot_sync(0xffffffffu, bnd >= rm - THR);

            const float* Bc = d_B + j;
            float s0 = 0.f, s1 = 0.f, s2 = 0.f, s3 = 0.f;
            for (int rc = 0; rc < 32; rc++) {
                if (!((mask >> rc) & 1u)) continue;
                int i = rc * 128 + ty;
                s0 += ex2f(fmaf(-k, Bc[(size_t)i * N],        sV[i]      + c));
                s1 += ex2f(fmaf(-k, Bc[(size_t)(i + 32) * N], sV[i + 32] + c));
                s2 += ex2f(fmaf(-k, Bc[(size_t)(i + 64) * N], sV[i + 64] + c));
                s3 += ex2f(fmaf(-k, Bc[(size_t)(i + 96) * N], sV[i + 96] + c));
            }
            sr[ty][tx] = (s0 + s1) + (s2 + s3);
            __syncthreads();
            float v = sr[tx][ty];
            for (int o = 16; o; o >>= 1) v += __shfl_down_sync(0xffffffffu, v, o);
            if (tx == 0) {
                int jj = bid * 32 + ty;
                d_G[jj] = ldcg(&d_G[jj]) - log2f(v);
            }
        }
        gsync(ep);
    }

    // ---- final: sum_ij P_ij * C_ij (same skipping; skipped weight negligible)
    for (int j = tid; j < N; j += TPB) sV[j] = ldcg(&d_G[j]);
    __syncthreads();
    {
        float m = fmaxf(fmaxf(sV[wid * 128 + ln],      sV[wid * 128 + ln + 32]),
                        fmaxf(sV[wid * 128 + ln + 64], sV[wid * 128 + ln + 96]));
        for (int o = 16; o; o >>= 1) m = fmaxf(m, __shfl_xor_sync(0xffffffffu, m, o));
        if (ln == 0) sMax[wid] = m;
    }
    __syncthreads();
    {
        const int i = bid * 32 + wid;
        const float c = ldcg(&d_F[i]) - 24.0f;
        float bnd = sMax[ln] - k * d_minBF[i * 32 + ln];
        float rm  = bnd;
        for (int o = 16; o; o >>= 1) rm = fmaxf(rm, __shfl_xor_sync(0xffffffffu, rm, o));
        unsigned mask = __ballot_sync(0xffffffffu, bnd >= rm - THR);

        const float4* Br = (const float4*)(d_B + (size_t)i * N);
        const float4* V4 = (const float4*)sV;
        float a0 = 0.f, a1 = 0.f, a2 = 0.f, a3 = 0.f;
        for (int s = 0; s < 32; s++) {
            if (!((mask >> s) & 1u)) continue;
            int t = s * 32 + ln;
            float4 b = Br[t];
            float4 g = V4[t];
            a0 = fmaf(ex2f(fmaf(-k, b.x, g.x + c)), b.x, a0);
            a1 = fmaf(ex2f(fmaf(-k, b.y, g.y + c)), b.y, a1);
            a2 = fmaf(ex2f(fmaf(-k, b.z, g.z + c)), b.z, a2);
            a3 = fmaf(ex2f(fmaf(-k, b.w, g.w + c)), b.w, a3);
        }
        float s = (a0 + a1) + (a2 + a3);
        for (int o = 16; o; o >>= 1) s += __shfl_down_sync(0xffffffffu, s, o);
        if (ln == 0) sr[0][wid] = s;
    }
    __syncthreads();
    if (tid < 32) {
        float s = sr[0][tid];
        for (int o = 16; o; o >>= 1) s += __shfl_down_sync(0xffffffffu, s, o);
        if (tid == 0) atomicAdd(&d_emd, (double)s);
    }
    gsync(ep);
    if (bid == 0 && tid == 0) out[0] = (float)d_emd;
}

// ---------------------------------------------------------------- launch
extern "C" void kernel_launch(void* const* d_in, const int* in_sizes, int n_in,
                              void* d_out, int out_size) {
    const float* x = (const float*)d_in[0];
    const float* y = (const float*)d_in[1];
    float* out = (float*)d_out;

    k_init<<<1, 1>>>();
    k_sort<<<1, 1024>>>(x, d_xs);
    k_sort<<<1, 1024>>>(y, d_ys);
    k_sum<<<N, 256>>>(d_xs, d_ys);
    k_eps<<<1, 1>>>();
    k_build<<<N, 256>>>(d_xs, d_ys);
    k_minc<<<NBLK, 1024>>>();
    k_persist<<<NBLK, TPB>>>(out);
}